// round 12
// baseline (speedup 1.0000x reference)
#include <cuda_runtime.h>
#include <cuda_bf16.h>
#include <math.h>

#define N_NODES 100000
#define N_EDGES 1600000
#define FEAT    128
#define NCLS    40
#define NBLK_SCAN 98   // ceil(100000/1024)

// ---------------- device scratch --------------------------------------------
__device__ __align__(16) float g_h1[(size_t)N_NODES * FEAT];
__device__ __align__(16) float g_h2[(size_t)N_NODES * FEAT];
__device__ __align__(16) float g_h3[(size_t)N_NODES * NCLS];
__device__ int   g_cnt[N_NODES];
__device__ int   g_cursor[N_NODES];
__device__ int   g_rowptr[N_NODES + 1];
__device__ int   g_scan_tmp[NBLK_SCAN * 1024];
__device__ int   g_blocksum[NBLK_SCAN];
__device__ int   g_blockoff[NBLK_SCAN];
__device__ __align__(8) int2 g_edge[N_EDGES];   // (src, coef-bits) packed
__device__ float g_dinv[N_NODES];
__device__ int   g_is64;

__device__ __forceinline__ float* pick_buf(int s, const float* ext) {
    if (s < 0) return (float*)ext;
    if (s == 0) return g_h1;
    if (s == 1) return g_h2;
    return g_h3;
}

__device__ __forceinline__ int load_edge(const void* ei, int which, int e, int is64) {
    if (is64)
        return (int)((const long long*)ei)[(size_t)which * N_EDGES + e];
    return ((const int*)ei)[(size_t)which * N_EDGES + e];
}

// ---------------- packed f32x2 helpers --------------------------------------
__device__ __forceinline__ unsigned long long f2dup(float a) {
    unsigned long long r;
    asm("mov.b64 %0, {%1, %1};" : "=l"(r) : "f"(a));
    return r;
}
__device__ __forceinline__ void f2unpack(unsigned long long v, float& a, float& b) {
    asm("mov.b64 {%0, %1}, %2;" : "=f"(a), "=f"(b) : "l"(v));
}
__device__ __forceinline__ unsigned long long f2fma(unsigned long long a,
                                                    unsigned long long b,
                                                    unsigned long long c) {
    unsigned long long d;
    asm("fma.rn.f32x2 %0, %1, %2, %3;" : "=l"(d) : "l"(a), "l"(b), "l"(c));
    return d;
}

// ---------------- CSR build -------------------------------------------------
// k_zero also performs the edge-dtype detection (thread 0 of block 0): reads
// the first 64 entries as int64; valid node-ids in both halves only if the
// buffer is truly int64 (int32 data combines adjacent words -> >= 2^32).
__global__ void k_zero(const long long* __restrict__ ei) {
    int i = blockIdx.x * blockDim.x + threadIdx.x;
    if (i < N_NODES) { g_cnt[i] = 0; g_cursor[i] = 0; }
    if (i == 0) {
        int ok = 1;
        for (int t = 0; t < 64; t++) {
            long long v = ei[t];
            if (v < 0 || v >= N_NODES) { ok = 0; break; }
        }
        g_is64 = ok;
    }
}

__global__ void k_count(const void* __restrict__ ei) {
    int e = blockIdx.x * blockDim.x + threadIdx.x;
    if (e < N_EDGES) {
        int is64 = g_is64;
        int d = load_edge(ei, 1, e, is64);
        atomicAdd(&g_cnt[d], 1);
    }
}

__global__ void k_scan_block() {
    __shared__ int sh[1024];
    int t = threadIdx.x;
    int g = blockIdx.x * 1024 + t;
    int v = (g < N_NODES) ? g_cnt[g] : 0;
    sh[t] = v;
    __syncthreads();
#pragma unroll
    for (int off = 1; off < 1024; off <<= 1) {
        int add = (t >= off) ? sh[t - off] : 0;
        __syncthreads();
        sh[t] += add;
        __syncthreads();
    }
    g_scan_tmp[g] = sh[t];
    if (t == 1023) g_blocksum[blockIdx.x] = sh[1023];
}

__global__ void k_scan_sums() {
    if (threadIdx.x == 0) {
        int run = 0;
        for (int i = 0; i < NBLK_SCAN; i++) {
            g_blockoff[i] = run;
            run += g_blocksum[i];
        }
    }
}

// rowptr finalize + dinv (fused; g_cnt is final after k_count)
__global__ void k_scan_add() {
    int g = blockIdx.x * blockDim.x + threadIdx.x;
    if (g <= N_NODES) {
        int v = (g == 0) ? 0 : g_scan_tmp[g - 1] + g_blockoff[(g - 1) >> 10];
        g_rowptr[g] = v;
        if (g < N_NODES) g_dinv[g] = rsqrtf((float)(g_cnt[g] + 1));  // +1 self loop
    }
}

__global__ void k_fill(const void* __restrict__ ei) {
    int e = blockIdx.x * blockDim.x + threadIdx.x;
    if (e < N_EDGES) {
        int is64 = g_is64;
        int s = load_edge(ei, 0, e, is64);
        int d = load_edge(ei, 1, e, is64);
        int pos = g_rowptr[d] + atomicAdd(&g_cursor[d], 1);
        float c = g_dinv[s] * g_dinv[d];
        g_edge[pos] = make_int2(s, __float_as_int(c));   // single 8B store
    }
}

// ---------------- GEMM 128x128 (H = X @ W), row-pair f32x2 ------------------
// block = 256 threads (8 warps), tile = 64 rows.
// smem holds X^T (k-major): xs_t[k][row]. Row-pairs load as one LDS.64
// broadcast (conflict-free), so x needs no packing; only W is dup-packed.
// Per thread: 8 rows (4 pairs) x 4 cols, acc as f32x2 over the row pair.
__global__ void k_gemm128(const float* __restrict__ Xext, int src_sel,
                          const float* __restrict__ W, int dst_sel) {
    __shared__ __align__(8) float xs_t[FEAT][64];   // 32KB
    const float* X = pick_buf(src_sel, Xext);
    float* H = pick_buf(dst_sel, nullptr);

    int tile = blockIdx.x * 64;

    // load + transpose: 64 rows x 128 cols = 2048 float4
    for (int idx = threadIdx.x; idx < 2048; idx += 256) {
        int r = idx & 63, c4 = idx >> 6;          // c4 in 0..31
        int row = tile + r;
        float4 v = make_float4(0.f, 0.f, 0.f, 0.f);
        if (row < N_NODES)
            v = __ldg((const float4*)(X + (size_t)row * FEAT) + c4);
        xs_t[c4 * 4 + 0][r] = v.x;
        xs_t[c4 * 4 + 1][r] = v.y;
        xs_t[c4 * 4 + 2][r] = v.z;
        xs_t[c4 * 4 + 3][r] = v.w;
    }
    __syncthreads();

    int warp = threadIdx.x >> 5, lane = threadIdx.x & 31;
    int r0 = warp * 8;          // 8 rows per warp-thread group (even -> 8B aligned)
    int c0 = lane * 4;          // 4 cols per lane

    unsigned long long acc[4][4];
#pragma unroll
    for (int p = 0; p < 4; p++)
#pragma unroll
        for (int c = 0; c < 4; c++) acc[p][c] = 0ULL;

#pragma unroll 2
    for (int k = 0; k < FEAT; k++) {
        float4 wv = __ldg((const float4*)(W + (size_t)k * FEAT) + lane);
        unsigned long long wd0 = f2dup(wv.x);
        unsigned long long wd1 = f2dup(wv.y);
        unsigned long long wd2 = f2dup(wv.z);
        unsigned long long wd3 = f2dup(wv.w);
#pragma unroll
        for (int p = 0; p < 4; p++) {
            unsigned long long xp =
                *(const unsigned long long*)&xs_t[k][r0 + 2 * p];  // broadcast LDS.64
            acc[p][0] = f2fma(xp, wd0, acc[p][0]);
            acc[p][1] = f2fma(xp, wd1, acc[p][1]);
            acc[p][2] = f2fma(xp, wd2, acc[p][2]);
            acc[p][3] = f2fma(xp, wd3, acc[p][3]);
        }
    }

#pragma unroll
    for (int p = 0; p < 4; p++) {
        int ra = tile + r0 + 2 * p;
        float4 oa, ob;
        f2unpack(acc[p][0], oa.x, ob.x);
        f2unpack(acc[p][1], oa.y, ob.y);
        f2unpack(acc[p][2], oa.z, ob.z);
        f2unpack(acc[p][3], oa.w, ob.w);
        if (ra < N_NODES)
            *(float4*)(H + (size_t)ra * FEAT + c0) = oa;
        if (ra + 1 < N_NODES)
            *(float4*)(H + (size_t)(ra + 1) * FEAT + c0) = ob;
    }
}

// ---------------- GEMM 128 -> 40 (H3 = X @ W3) ------------------------------
__global__ void k_gemm40(int src_sel, const float* __restrict__ W3) {
    __shared__ __align__(16) float xs[32][FEAT];
    const float* X = pick_buf(src_sel, nullptr);
    float* H = g_h3;

    int tile = blockIdx.x * 32;
    for (int idx = threadIdx.x; idx < 32 * 32; idx += blockDim.x) {
        int r = idx >> 5, c4 = idx & 31;
        int row = tile + r;
        float4 v = make_float4(0.f, 0.f, 0.f, 0.f);
        if (row < N_NODES)
            v = __ldg((const float4*)(X + (size_t)row * FEAT) + c4);
        *(float4*)&xs[r][c4 * 4] = v;
    }
    __syncthreads();

    int warp = threadIdx.x >> 5, lane = threadIdx.x & 31;
    bool hi = lane < (NCLS - 32);
    int r0 = warp * 4;

    float acc0[4] = {0.f, 0.f, 0.f, 0.f};
    float acc1[4] = {0.f, 0.f, 0.f, 0.f};

#pragma unroll 4
    for (int k = 0; k < FEAT; k++) {
        float w0 = __ldg(W3 + k * NCLS + lane);
        float w1 = hi ? __ldg(W3 + k * NCLS + 32 + lane) : 0.f;
#pragma unroll
        for (int j = 0; j < 4; j++) {
            float xv = xs[r0 + j][k];
            acc0[j] = fmaf(xv, w0, acc0[j]);
            acc1[j] = fmaf(xv, w1, acc1[j]);
        }
    }

#pragma unroll
    for (int j = 0; j < 4; j++) {
        int row = tile + r0 + j;
        if (row < N_NODES) {
            H[(size_t)row * NCLS + lane] = acc0[j];
            if (hi) H[(size_t)row * NCLS + 32 + lane] = acc1[j];
        }
    }
}

// ---------------- aggregation 128-wide (one warp per node) ------------------
__global__ void k_agg128(int src_sel, int dst_sel,
                         const float* __restrict__ B, int do_relu) {
    int w = (blockIdx.x * blockDim.x + threadIdx.x) >> 5;
    if (w >= N_NODES) return;
    int lane = threadIdx.x & 31;

    const float* H = pick_buf(src_sel, nullptr);
    float* O = pick_buf(dst_sel, nullptr);

    int s = g_rowptr[w];
    int e = g_rowptr[w + 1];
    float di = g_dinv[w];
    float cself = di * di;

    float4 hv = __ldg((const float4*)(H + (size_t)w * FEAT) + lane);
    float4 acc;
    acc.x = cself * hv.x; acc.y = cself * hv.y;
    acc.z = cself * hv.z; acc.w = cself * hv.w;

    for (int base = s; base < e; base += 32) {
        int idx = base + lane;
        int sj = 0; float cj = 0.f;
        if (idx < e) {
            int2 eg = __ldg(&g_edge[idx]);   // coalesced 8B
            sj = eg.x; cj = __int_as_float(eg.y);
        }
        int m = e - base; if (m > 32) m = 32;
        for (int t = 0; t < m; t++) {
            int   sb = __shfl_sync(0xffffffffu, sj, t);
            float cb = __shfl_sync(0xffffffffu, cj, t);
            float4 v = __ldg((const float4*)(H + (size_t)sb * FEAT) + lane);
            acc.x = fmaf(cb, v.x, acc.x);
            acc.y = fmaf(cb, v.y, acc.y);
            acc.z = fmaf(cb, v.z, acc.z);
            acc.w = fmaf(cb, v.w, acc.w);
        }
    }

    float4 b4 = __ldg((const float4*)B + lane);
    acc.x += b4.x; acc.y += b4.y; acc.z += b4.z; acc.w += b4.w;
    if (do_relu) {
        acc.x = fmaxf(acc.x, 0.f); acc.y = fmaxf(acc.y, 0.f);
        acc.z = fmaxf(acc.z, 0.f); acc.w = fmaxf(acc.w, 0.f);
    }
    *((float4*)(O + (size_t)w * FEAT) + lane) = acc;
}

// ---------------- aggregation 40-wide + fused log_softmax -------------------
__global__ void k_agg40_lsm(const float* __restrict__ B3, float* __restrict__ O) {
    int w = (blockIdx.x * blockDim.x + threadIdx.x) >> 5;
    if (w >= N_NODES) return;
    int lane = threadIdx.x & 31;
    bool hi = lane < (NCLS - 32);

    const float* H = g_h3;
    int s = g_rowptr[w];
    int e = g_rowptr[w + 1];
    float di = g_dinv[w];
    float cself = di * di;

    const float* rself = H + (size_t)w * NCLS;
    float a0 = cself * __ldg(rself + lane);
    float a1 = hi ? cself * __ldg(rself + 32 + lane) : 0.f;

    for (int base = s; base < e; base += 32) {
        int idx = base + lane;
        int sj = 0; float cj = 0.f;
        if (idx < e) {
            int2 eg = __ldg(&g_edge[idx]);
            sj = eg.x; cj = __int_as_float(eg.y);
        }
        int m = e - base; if (m > 32) m = 32;
        for (int t = 0; t < m; t++) {
            int   sb = __shfl_sync(0xffffffffu, sj, t);
            float cb = __shfl_sync(0xffffffffu, cj, t);
            const float* rs = H + (size_t)sb * NCLS;
            a0 = fmaf(cb, __ldg(rs + lane), a0);
            if (hi) a1 = fmaf(cb, __ldg(rs + 32 + lane), a1);
        }
    }

    a0 += __ldg(B3 + lane);
    if (hi) a1 += __ldg(B3 + 32 + lane);

    float mv = a0;
    if (hi) mv = fmaxf(mv, a1);
#pragma unroll
    for (int o = 16; o > 0; o >>= 1)
        mv = fmaxf(mv, __shfl_xor_sync(0xffffffffu, mv, o));

    float sv = expf(a0 - mv) + (hi ? expf(a1 - mv) : 0.f);
#pragma unroll
    for (int o = 16; o > 0; o >>= 1)
        sv += __shfl_xor_sync(0xffffffffu, sv, o);

    float L = mv + logf(sv);
    O[(size_t)w * NCLS + lane] = a0 - L;
    if (hi) O[(size_t)w * NCLS + 32 + lane] = a1 - L;
}

// ---------------- launch ----------------------------------------------------
extern "C" void kernel_launch(void* const* d_in, const int* in_sizes, int n_in,
                              void* d_out, int out_size) {
    const float* x  = (const float*)d_in[0];
    const void*  ei = d_in[1];                  // int32 or int64 (device-detected)
    const float* W1 = (const float*)d_in[2];
    const float* b1 = (const float*)d_in[3];
    const float* W2 = (const float*)d_in[4];
    const float* b2 = (const float*)d_in[5];
    const float* W3 = (const float*)d_in[6];
    const float* b3 = (const float*)d_in[7];
    float* out = (float*)d_out;

    // --- CSR build (kernels only; capturable) ---
    k_zero<<<(N_NODES + 255) / 256, 256>>>((const long long*)ei);
    k_count<<<(N_EDGES + 255) / 256, 256>>>(ei);
    k_scan_block<<<NBLK_SCAN, 1024>>>();
    k_scan_sums<<<1, 32>>>();
    k_scan_add<<<(N_NODES + 1 + 255) / 256, 256>>>();
    k_fill<<<(N_EDGES + 255) / 256, 256>>>(ei);

    const int gemm128_grid = (N_NODES + 63) / 64;        // 1563
    const int gemm40_grid  = (N_NODES + 31) / 32;        // 3125
    const int agg_grid     = (N_NODES * 32 + 255) / 256; // 12500

    // layer 1: h1 = x @ W1 ; h2 = relu(agg(h1) + b1)
    k_gemm128<<<gemm128_grid, 256>>>(x, -1, W1, 0);
    k_agg128<<<agg_grid, 256>>>(0, 1, b1, 1);
    // layer 2: h1 = h2 @ W2 ; h2 = relu(agg(h1) + b2)
    k_gemm128<<<gemm128_grid, 256>>>(nullptr, 1, W2, 0);
    k_agg128<<<agg_grid, 256>>>(0, 1, b2, 1);
    // layer 3: h3 = h2 @ W3 ; out = log_softmax(agg(h3) + b3)
    k_gemm40<<<gemm40_grid, 256>>>(1, W3);
    k_agg40_lsm<<<agg_grid, 256>>>(b3, out);
}

// round 13
// speedup vs baseline: 1.0115x; 1.0115x over previous
#include <cuda_runtime.h>
#include <cuda_bf16.h>
#include <math.h>

#define N_NODES 100000
#define N_EDGES 1600000
#define FEAT    128
#define NCLS    40
#define NBLK_SCAN 98   // ceil(100000/1024)

// ---------------- device scratch --------------------------------------------
__device__ __align__(16) float g_h1[(size_t)N_NODES * FEAT];
__device__ __align__(16) float g_h2[(size_t)N_NODES * FEAT];
__device__ __align__(16) float g_h3[(size_t)N_NODES * NCLS];
__device__ int   g_cnt[N_NODES];
__device__ int   g_cursor[N_NODES];
__device__ int   g_rowptr[N_NODES + 1];
__device__ int   g_scan_tmp[NBLK_SCAN * 1024];
__device__ int   g_blocksum[NBLK_SCAN];
__device__ int   g_blockoff[NBLK_SCAN];
__device__ __align__(8) int2 g_edge[N_EDGES];   // (src, coef-bits) packed
__device__ float g_dinv[N_NODES];
__device__ int   g_is64;

__device__ __forceinline__ float* pick_buf(int s, const float* ext) {
    if (s < 0) return (float*)ext;
    if (s == 0) return g_h1;
    if (s == 1) return g_h2;
    return g_h3;
}

__device__ __forceinline__ int load_edge(const void* ei, int which, int e, int is64) {
    if (is64)
        return (int)((const long long*)ei)[(size_t)which * N_EDGES + e];
    return ((const int*)ei)[(size_t)which * N_EDGES + e];
}

// ---------------- packed f32x2 helpers --------------------------------------
__device__ __forceinline__ unsigned long long f2dup(float a) {
    unsigned long long r;
    asm("mov.b64 %0, {%1, %1};" : "=l"(r) : "f"(a));
    return r;
}
__device__ __forceinline__ void f2unpack(unsigned long long v, float& a, float& b) {
    asm("mov.b64 {%0, %1}, %2;" : "=f"(a), "=f"(b) : "l"(v));
}
__device__ __forceinline__ unsigned long long f2fma(unsigned long long a,
                                                    unsigned long long b,
                                                    unsigned long long c) {
    unsigned long long d;
    asm("fma.rn.f32x2 %0, %1, %2, %3;" : "=l"(d) : "l"(a), "l"(b), "l"(c));
    return d;
}

// ---------------- CSR build -------------------------------------------------
// k_zero also performs the edge-dtype detection (thread 0 of block 0): reads
// the first 64 entries as int64; valid node-ids in both halves only if the
// buffer is truly int64 (int32 data combines adjacent words -> >= 2^32).
__global__ void k_zero(const long long* __restrict__ ei) {
    int i = blockIdx.x * blockDim.x + threadIdx.x;
    if (i < N_NODES) { g_cnt[i] = 0; g_cursor[i] = 0; }
    if (i == 0) {
        int ok = 1;
        for (int t = 0; t < 64; t++) {
            long long v = ei[t];
            if (v < 0 || v >= N_NODES) { ok = 0; break; }
        }
        g_is64 = ok;
    }
}

__global__ void k_count(const void* __restrict__ ei) {
    int e = blockIdx.x * blockDim.x + threadIdx.x;
    if (e < N_EDGES) {
        int is64 = g_is64;
        int d = load_edge(ei, 1, e, is64);
        atomicAdd(&g_cnt[d], 1);
    }
}

__global__ void k_scan_block() {
    __shared__ int sh[1024];
    int t = threadIdx.x;
    int g = blockIdx.x * 1024 + t;
    int v = (g < N_NODES) ? g_cnt[g] : 0;
    sh[t] = v;
    __syncthreads();
#pragma unroll
    for (int off = 1; off < 1024; off <<= 1) {
        int add = (t >= off) ? sh[t - off] : 0;
        __syncthreads();
        sh[t] += add;
        __syncthreads();
    }
    g_scan_tmp[g] = sh[t];
    if (t == 1023) g_blocksum[blockIdx.x] = sh[1023];
}

__global__ void k_scan_sums() {
    if (threadIdx.x == 0) {
        int run = 0;
        for (int i = 0; i < NBLK_SCAN; i++) {
            g_blockoff[i] = run;
            run += g_blocksum[i];
        }
    }
}

// rowptr finalize + dinv (fused; g_cnt is final after k_count)
__global__ void k_scan_add() {
    int g = blockIdx.x * blockDim.x + threadIdx.x;
    if (g <= N_NODES) {
        int v = (g == 0) ? 0 : g_scan_tmp[g - 1] + g_blockoff[(g - 1) >> 10];
        g_rowptr[g] = v;
        if (g < N_NODES) g_dinv[g] = rsqrtf((float)(g_cnt[g] + 1));  // +1 self loop
    }
}

__global__ void k_fill(const void* __restrict__ ei) {
    int e = blockIdx.x * blockDim.x + threadIdx.x;
    if (e < N_EDGES) {
        int is64 = g_is64;
        int s = load_edge(ei, 0, e, is64);
        int d = load_edge(ei, 1, e, is64);
        int pos = g_rowptr[d] + atomicAdd(&g_cursor[d], 1);
        float c = g_dinv[s] * g_dinv[d];
        g_edge[pos] = make_int2(s, __float_as_int(c));   // single 8B store
    }
}

// ---------------- GEMM 128x128 (H = X @ W), row-pair f32x2 ------------------
// block = 256 threads (8 warps), tile = 64 rows.
// smem holds X^T (k-major): xs_t[k][row]. Row-pairs load as one LDS.64
// broadcast (conflict-free), so x needs no packing; only W is dup-packed.
// Per thread: 8 rows (4 pairs) x 4 cols, acc as f32x2 over the row pair.
__global__ void k_gemm128(const float* __restrict__ Xext, int src_sel,
                          const float* __restrict__ W, int dst_sel) {
    __shared__ __align__(8) float xs_t[FEAT][64];   // 32KB
    const float* X = pick_buf(src_sel, Xext);
    float* H = pick_buf(dst_sel, nullptr);

    int tile = blockIdx.x * 64;

    // load + transpose: 64 rows x 128 cols = 2048 float4
    for (int idx = threadIdx.x; idx < 2048; idx += 256) {
        int r = idx & 63, c4 = idx >> 6;          // c4 in 0..31
        int row = tile + r;
        float4 v = make_float4(0.f, 0.f, 0.f, 0.f);
        if (row < N_NODES)
            v = __ldg((const float4*)(X + (size_t)row * FEAT) + c4);
        xs_t[c4 * 4 + 0][r] = v.x;
        xs_t[c4 * 4 + 1][r] = v.y;
        xs_t[c4 * 4 + 2][r] = v.z;
        xs_t[c4 * 4 + 3][r] = v.w;
    }
    __syncthreads();

    int warp = threadIdx.x >> 5, lane = threadIdx.x & 31;
    int r0 = warp * 8;          // 8 rows per warp-thread group (even -> 8B aligned)
    int c0 = lane * 4;          // 4 cols per lane

    unsigned long long acc[4][4];
#pragma unroll
    for (int p = 0; p < 4; p++)
#pragma unroll
        for (int c = 0; c < 4; c++) acc[p][c] = 0ULL;

#pragma unroll 2
    for (int k = 0; k < FEAT; k++) {
        float4 wv = __ldg((const float4*)(W + (size_t)k * FEAT) + lane);
        unsigned long long wd0 = f2dup(wv.x);
        unsigned long long wd1 = f2dup(wv.y);
        unsigned long long wd2 = f2dup(wv.z);
        unsigned long long wd3 = f2dup(wv.w);
#pragma unroll
        for (int p = 0; p < 4; p++) {
            unsigned long long xp =
                *(const unsigned long long*)&xs_t[k][r0 + 2 * p];  // broadcast LDS.64
            acc[p][0] = f2fma(xp, wd0, acc[p][0]);
            acc[p][1] = f2fma(xp, wd1, acc[p][1]);
            acc[p][2] = f2fma(xp, wd2, acc[p][2]);
            acc[p][3] = f2fma(xp, wd3, acc[p][3]);
        }
    }

#pragma unroll
    for (int p = 0; p < 4; p++) {
        int ra = tile + r0 + 2 * p;
        float4 oa, ob;
        f2unpack(acc[p][0], oa.x, ob.x);
        f2unpack(acc[p][1], oa.y, ob.y);
        f2unpack(acc[p][2], oa.z, ob.z);
        f2unpack(acc[p][3], oa.w, ob.w);
        if (ra < N_NODES)
            *(float4*)(H + (size_t)ra * FEAT + c0) = oa;
        if (ra + 1 < N_NODES)
            *(float4*)(H + (size_t)(ra + 1) * FEAT + c0) = ob;
    }
}

// ---------------- GEMM 128 -> 40 (H3 = X @ W3) ------------------------------
__global__ void k_gemm40(int src_sel, const float* __restrict__ W3) {
    __shared__ __align__(16) float xs[32][FEAT];
    const float* X = pick_buf(src_sel, nullptr);
    float* H = g_h3;

    int tile = blockIdx.x * 32;
    for (int idx = threadIdx.x; idx < 32 * 32; idx += blockDim.x) {
        int r = idx >> 5, c4 = idx & 31;
        int row = tile + r;
        float4 v = make_float4(0.f, 0.f, 0.f, 0.f);
        if (row < N_NODES)
            v = __ldg((const float4*)(X + (size_t)row * FEAT) + c4);
        *(float4*)&xs[r][c4 * 4] = v;
    }
    __syncthreads();

    int warp = threadIdx.x >> 5, lane = threadIdx.x & 31;
    bool hi = lane < (NCLS - 32);
    int r0 = warp * 4;

    float acc0[4] = {0.f, 0.f, 0.f, 0.f};
    float acc1[4] = {0.f, 0.f, 0.f, 0.f};

#pragma unroll 4
    for (int k = 0; k < FEAT; k++) {
        float w0 = __ldg(W3 + k * NCLS + lane);
        float w1 = hi ? __ldg(W3 + k * NCLS + 32 + lane) : 0.f;
#pragma unroll
        for (int j = 0; j < 4; j++) {
            float xv = xs[r0 + j][k];
            acc0[j] = fmaf(xv, w0, acc0[j]);
            acc1[j] = fmaf(xv, w1, acc1[j]);
        }
    }

#pragma unroll
    for (int j = 0; j < 4; j++) {
        int row = tile + r0 + j;
        if (row < N_NODES) {
            H[(size_t)row * NCLS + lane] = acc0[j];
            if (hi) H[(size_t)row * NCLS + 32 + lane] = acc1[j];
        }
    }
}

// ---------------- aggregation 128-wide (one warp per node) ------------------
__global__ void k_agg128(int src_sel, int dst_sel,
                         const float* __restrict__ B, int do_relu) {
    int w = (blockIdx.x * blockDim.x + threadIdx.x) >> 5;
    if (w >= N_NODES) return;
    int lane = threadIdx.x & 31;

    const float* H = pick_buf(src_sel, nullptr);
    float* O = pick_buf(dst_sel, nullptr);

    int s = g_rowptr[w];
    int e = g_rowptr[w + 1];
    float di = g_dinv[w];
    float cself = di * di;

    float4 hv = __ldg((const float4*)(H + (size_t)w * FEAT) + lane);
    float4 acc;
    acc.x = cself * hv.x; acc.y = cself * hv.y;
    acc.z = cself * hv.z; acc.w = cself * hv.w;

    for (int base = s; base < e; base += 32) {
        int idx = base + lane;
        int sj = 0; float cj = 0.f;
        if (idx < e) {
            int2 eg = __ldg(&g_edge[idx]);   // coalesced 8B
            sj = eg.x; cj = __int_as_float(eg.y);
        }
        int m = e - base; if (m > 32) m = 32;
        for (int t = 0; t < m; t++) {
            int   sb = __shfl_sync(0xffffffffu, sj, t);
            float cb = __shfl_sync(0xffffffffu, cj, t);
            float4 v = __ldg((const float4*)(H + (size_t)sb * FEAT) + lane);
            acc.x = fmaf(cb, v.x, acc.x);
            acc.y = fmaf(cb, v.y, acc.y);
            acc.z = fmaf(cb, v.z, acc.z);
            acc.w = fmaf(cb, v.w, acc.w);
        }
    }

    float4 b4 = __ldg((const float4*)B + lane);
    acc.x += b4.x; acc.y += b4.y; acc.z += b4.z; acc.w += b4.w;
    if (do_relu) {
        acc.x = fmaxf(acc.x, 0.f); acc.y = fmaxf(acc.y, 0.f);
        acc.z = fmaxf(acc.z, 0.f); acc.w = fmaxf(acc.w, 0.f);
    }
    *((float4*)(O + (size_t)w * FEAT) + lane) = acc;
}

// ---------------- aggregation 40-wide + fused log_softmax -------------------
__global__ void k_agg40_lsm(const float* __restrict__ B3, float* __restrict__ O) {
    int w = (blockIdx.x * blockDim.x + threadIdx.x) >> 5;
    if (w >= N_NODES) return;
    int lane = threadIdx.x & 31;
    bool hi = lane < (NCLS - 32);

    const float* H = g_h3;
    int s = g_rowptr[w];
    int e = g_rowptr[w + 1];
    float di = g_dinv[w];
    float cself = di * di;

    const float* rself = H + (size_t)w * NCLS;
    float a0 = cself * __ldg(rself + lane);
    float a1 = hi ? cself * __ldg(rself + 32 + lane) : 0.f;

    for (int base = s; base < e; base += 32) {
        int idx = base + lane;
        int sj = 0; float cj = 0.f;
        if (idx < e) {
            int2 eg = __ldg(&g_edge[idx]);
            sj = eg.x; cj = __int_as_float(eg.y);
        }
        int m = e - base; if (m > 32) m = 32;
        for (int t = 0; t < m; t++) {
            int   sb = __shfl_sync(0xffffffffu, sj, t);
            float cb = __shfl_sync(0xffffffffu, cj, t);
            const float* rs = H + (size_t)sb * NCLS;
            a0 = fmaf(cb, __ldg(rs + lane), a0);
            if (hi) a1 = fmaf(cb, __ldg(rs + 32 + lane), a1);
        }
    }

    a0 += __ldg(B3 + lane);
    if (hi) a1 += __ldg(B3 + 32 + lane);

    float mv = a0;
    if (hi) mv = fmaxf(mv, a1);
#pragma unroll
    for (int o = 16; o > 0; o >>= 1)
        mv = fmaxf(mv, __shfl_xor_sync(0xffffffffu, mv, o));

    float sv = expf(a0 - mv) + (hi ? expf(a1 - mv) : 0.f);
#pragma unroll
    for (int o = 16; o > 0; o >>= 1)
        sv += __shfl_xor_sync(0xffffffffu, sv, o);

    float L = mv + logf(sv);
    O[(size_t)w * NCLS + lane] = a0 - L;
    if (hi) O[(size_t)w * NCLS + 32 + lane] = a1 - L;
}

// ---------------- launch ----------------------------------------------------
extern "C" void kernel_launch(void* const* d_in, const int* in_sizes, int n_in,
                              void* d_out, int out_size) {
    const float* x  = (const float*)d_in[0];
    const void*  ei = d_in[1];                  // int32 or int64 (device-detected)
    const float* W1 = (const float*)d_in[2];
    const float* b1 = (const float*)d_in[3];
    const float* W2 = (const float*)d_in[4];
    const float* b2 = (const float*)d_in[5];
    const float* W3 = (const float*)d_in[6];
    const float* b3 = (const float*)d_in[7];
    float* out = (float*)d_out;

    // --- CSR build (kernels only; capturable) ---
    k_zero<<<(N_NODES + 255) / 256, 256>>>((const long long*)ei);
    k_count<<<(N_EDGES + 255) / 256, 256>>>(ei);
    k_scan_block<<<NBLK_SCAN, 1024>>>();
    k_scan_sums<<<1, 32>>>();
    k_scan_add<<<(N_NODES + 1 + 255) / 256, 256>>>();
    k_fill<<<(N_EDGES + 255) / 256, 256>>>(ei);

    const int gemm128_grid = (N_NODES + 63) / 64;        // 1563
    const int gemm40_grid  = (N_NODES + 31) / 32;        // 3125
    const int agg_grid     = (N_NODES * 32 + 255) / 256; // 12500

    // layer 1: h1 = x @ W1 ; h2 = relu(agg(h1) + b1)
    k_gemm128<<<gemm128_grid, 256>>>(x, -1, W1, 0);
    k_agg128<<<agg_grid, 256>>>(0, 1, b1, 1);
    // layer 2: h1 = h2 @ W2 ; h2 = relu(agg(h1) + b2)
    k_gemm128<<<gemm128_grid, 256>>>(nullptr, 1, W2, 0);
    k_agg128<<<agg_grid, 256>>>(0, 1, b2, 1);
    // layer 3: h3 = h2 @ W3 ; out = log_softmax(agg(h3) + b3)
    k_gemm40<<<gemm40_grid, 256>>>(1, W3);
    k_agg40_lsm<<<agg_grid, 256>>>(b3, out);
}